// round 1
// baseline (speedup 1.0000x reference)
#include <cuda_runtime.h>
#include <cstdint>

#define N_TOK 4096
#define DIM   1024
#define HID   1024
#define NE    8
#define NSEG  9   // 8 routed experts + 1 shared "expert"

// ---------------- scratch (device globals; no allocation allowed) ----------
__device__ int   g_cnt[NSEG];
__device__ int   g_assign_token[NE * N_TOK];
__device__ int   g_assign_slot [NE * N_TOK];
__device__ int   g_top_e[N_TOK * 2];
__device__ float g_top_w[N_TOK * 2];
__device__ float g_gbuf[(size_t)NSEG * N_TOK * HID];  // gate, then h in-place
__device__ float g_ubuf[(size_t)NSEG * N_TOK * HID];  // up
__device__ float g_rbuf[(size_t)3 * N_TOK * DIM];     // slot0, slot1, shared

// ---------------- init ------------------------------------------------------
__global__ void zero_kernel() {
    int t = threadIdx.x;
    if (t < NE) g_cnt[t] = 0;
    if (t == NE) g_cnt[NE] = N_TOK;  // shared expert covers all tokens
}

// ---------------- router: logits -> sigmoid -> top2 -------------------------
// block = 256 threads = 8 warps; warp w handles token blockIdx.x*8 + w.
// loop bias (loop_emb @ Wr[DIM:2*DIM]) computed per block (warp w -> bias[w]).
__global__ __launch_bounds__(256) void router_kernel(
    const float* __restrict__ X, const float* __restrict__ Wr,
    const float* __restrict__ loop_table, const int* __restrict__ loop_idx)
{
    __shared__ float s_bias[NE];
    const int warp = threadIdx.x >> 5, lane = threadIdx.x & 31;
    const int li = loop_idx[0];
    const float* le = loop_table + (size_t)li * DIM;

    float b = 0.f;
    for (int d = lane; d < DIM; d += 32)
        b += le[d] * Wr[(size_t)(DIM + d) * NE + warp];
    #pragma unroll
    for (int o = 16; o; o >>= 1) b += __shfl_xor_sync(~0u, b, o);
    if (lane == 0) s_bias[warp] = b;
    __syncthreads();

    const int t = blockIdx.x * 8 + warp;
    const float* xr = X + (size_t)t * DIM;
    float acc[NE];
    #pragma unroll
    for (int e = 0; e < NE; e++) acc[e] = 0.f;
    for (int d = lane; d < DIM; d += 32) {
        float xv = xr[d];
        const float* wrow = Wr + (size_t)d * NE;
        #pragma unroll
        for (int e = 0; e < NE; e++) acc[e] += xv * wrow[e];
    }
    #pragma unroll
    for (int e = 0; e < NE; e++)
        #pragma unroll
        for (int o = 16; o; o >>= 1) acc[e] += __shfl_xor_sync(~0u, acc[e], o);

    if (lane == 0) {
        float p[NE];
        #pragma unroll
        for (int e = 0; e < NE; e++)
            p[e] = 1.f / (1.f + expf(-(acc[e] + s_bias[e])));
        // top-2, first-occurrence ties (matches jax.lax.top_k)
        int i0 = 0; float v0 = p[0];
        #pragma unroll
        for (int e = 1; e < NE; e++) if (p[e] > v0) { v0 = p[e]; i0 = e; }
        int i1 = -1; float v1 = -1e30f;
        #pragma unroll
        for (int e = 0; e < NE; e++) {
            if (e == i0) continue;
            if (p[e] > v1) { v1 = p[e]; i1 = e; }
        }
        g_top_e[t * 2 + 0] = i0;  g_top_e[t * 2 + 1] = i1;
        g_top_w[t * 2 + 0] = v0;  g_top_w[t * 2 + 1] = v1;
    }
}

// ---------------- dispatch: build per-expert segments -----------------------
__global__ void dispatch_kernel() {
    int t = blockIdx.x * blockDim.x + threadIdx.x;
    if (t >= N_TOK) return;
    #pragma unroll
    for (int k = 0; k < 2; k++) {
        int e = g_top_e[t * 2 + k];
        int pos = atomicAdd(&g_cnt[e], 1);
        g_assign_token[e * N_TOK + pos] = t;
        g_assign_slot [e * N_TOK + pos] = k;
    }
}

// ---------------- GEMM1: gathered X @ {Wg|Wu}[e] -> gbuf/ubuf ---------------
// 128x128x8 tile, 256 threads, 8x8 per-thread, global prefetch.
// grid: x = 0..15 (0-7: gate n-tiles, 8-15: up n-tiles), y = m-tile, z = expert.
__global__ __launch_bounds__(256) void gemm1_kernel(
    const float* __restrict__ X,
    const float* __restrict__ Wg, const float* __restrict__ Wu,
    const float* __restrict__ sg, const float* __restrict__ su)
{
    __shared__ float As[8 * 128];
    __shared__ float Bs[8 * 128];
    __shared__ int   s_token[128];

    const int e   = blockIdx.z;
    const int cnt = g_cnt[e];
    const int m0  = blockIdx.y * 128;
    if (m0 >= cnt) return;
    const bool isU = blockIdx.x >= 8;
    const int n0  = (blockIdx.x & 7) * 128;

    const float* B = (e < NE) ? ((isU ? Wu : Wg) + (size_t)e * DIM * HID)
                              : (isU ? su : sg);
    float* C = (isU ? g_ubuf : g_gbuf) + (size_t)e * N_TOK * HID;

    const int tid = threadIdx.x;
    if (tid < 128) {
        int r = m0 + tid;
        int tok;
        if (e < NE) tok = (r < cnt) ? g_assign_token[e * N_TOK + r] : 0;
        else        tok = r;
        s_token[tid] = tok;
    }
    __syncthreads();

    const int ar = tid >> 1;
    const int ak = (tid & 1) * 4;
    const float* aptr = X + (size_t)s_token[ar] * DIM + ak;
    const int bk = tid >> 5;
    const int bc = (tid & 31) * 4;
    const float* bptr = B + (size_t)bk * HID + n0 + bc;

    const int tx = tid & 15, ty = tid >> 4;
    float acc[8][8];
    #pragma unroll
    for (int i = 0; i < 8; i++)
        #pragma unroll
        for (int j = 0; j < 8; j++) acc[i][j] = 0.f;

    float4 pa = *(const float4*)(aptr);
    float4 pb = *(const float4*)(bptr);

    const int NKT = DIM / 8;
    for (int kt = 0; kt < NKT; kt++) {
        As[(ak + 0) * 128 + ar] = pa.x;
        As[(ak + 1) * 128 + ar] = pa.y;
        As[(ak + 2) * 128 + ar] = pa.z;
        As[(ak + 3) * 128 + ar] = pa.w;
        *(float4*)&Bs[bk * 128 + bc] = pb;
        __syncthreads();
        if (kt + 1 < NKT) {
            pa = *(const float4*)(aptr + (kt + 1) * 8);
            pb = *(const float4*)(bptr + (size_t)(kt + 1) * 8 * HID);
        }
        #pragma unroll
        for (int k = 0; k < 8; k++) {
            float a[8], bb[8];
            *(float4*)&a[0]  = *(const float4*)&As[k * 128 + ty * 8];
            *(float4*)&a[4]  = *(const float4*)&As[k * 128 + ty * 8 + 4];
            *(float4*)&bb[0] = *(const float4*)&Bs[k * 128 + tx * 8];
            *(float4*)&bb[4] = *(const float4*)&Bs[k * 128 + tx * 8 + 4];
            #pragma unroll
            for (int i = 0; i < 8; i++)
                #pragma unroll
                for (int j = 0; j < 8; j++) acc[i][j] += a[i] * bb[j];
        }
        __syncthreads();
    }

    #pragma unroll
    for (int i = 0; i < 8; i++) {
        int r = m0 + ty * 8 + i;
        if (r < cnt) {
            float* cp = C + (size_t)r * HID + n0 + tx * 8;
            *(float4*)(cp)     = make_float4(acc[i][0], acc[i][1], acc[i][2], acc[i][3]);
            *(float4*)(cp + 4) = make_float4(acc[i][4], acc[i][5], acc[i][6], acc[i][7]);
        }
    }
}

// ---------------- activation: h = silu(gate) * up (in-place into gbuf) ------
__global__ void act_kernel() {
    int i4  = blockIdx.x * 256 + threadIdx.x;   // float4 index
    int row = i4 >> 8;                          // 256 float4 per row (HID=1024)
    int e   = row >> 12;
    int r   = row & (N_TOK - 1);
    if (r >= g_cnt[e]) return;
    float4 g = ((const float4*)g_gbuf)[i4];
    float4 u = ((const float4*)g_ubuf)[i4];
    float4 h;
    h.x = g.x / (1.f + __expf(-g.x)) * u.x;
    h.y = g.y / (1.f + __expf(-g.y)) * u.y;
    h.z = g.z / (1.f + __expf(-g.z)) * u.z;
    h.w = g.w / (1.f + __expf(-g.w)) * u.w;
    ((float4*)g_gbuf)[i4] = h;
}

// ---------------- GEMM2: h @ Wd[e] -> scattered into rbuf slots -------------
__global__ __launch_bounds__(256) void gemm2_kernel(
    const float* __restrict__ Wd, const float* __restrict__ sd)
{
    __shared__ float As[8 * 128];
    __shared__ float Bs[8 * 128];
    __shared__ int   s_dst[128];

    const int e   = blockIdx.z;
    const int cnt = g_cnt[e];
    const int m0  = blockIdx.y * 128;
    if (m0 >= cnt) return;
    const int n0  = blockIdx.x * 128;

    const float* Abase = g_gbuf + (size_t)e * N_TOK * HID;
    const float* B = (e < NE) ? (Wd + (size_t)e * HID * DIM) : sd;

    const int tid = threadIdx.x;
    if (tid < 128) {
        int r = m0 + tid;
        int dst = 0;
        if (r < cnt) {
            if (e < NE)
                dst = g_assign_slot[e * N_TOK + r] * N_TOK +
                      g_assign_token[e * N_TOK + r];
            else
                dst = 2 * N_TOK + r;
        }
        s_dst[tid] = dst;
    }
    __syncthreads();

    const int ar = tid >> 1;
    const int ak = (tid & 1) * 4;
    const float* aptr = Abase + (size_t)(m0 + ar) * HID + ak;
    const int bk = tid >> 5;
    const int bc = (tid & 31) * 4;
    const float* bptr = B + (size_t)bk * DIM + n0 + bc;

    const int tx = tid & 15, ty = tid >> 4;
    float acc[8][8];
    #pragma unroll
    for (int i = 0; i < 8; i++)
        #pragma unroll
        for (int j = 0; j < 8; j++) acc[i][j] = 0.f;

    float4 pa = *(const float4*)(aptr);
    float4 pb = *(const float4*)(bptr);

    const int NKT = HID / 8;
    for (int kt = 0; kt < NKT; kt++) {
        As[(ak + 0) * 128 + ar] = pa.x;
        As[(ak + 1) * 128 + ar] = pa.y;
        As[(ak + 2) * 128 + ar] = pa.z;
        As[(ak + 3) * 128 + ar] = pa.w;
        *(float4*)&Bs[bk * 128 + bc] = pb;
        __syncthreads();
        if (kt + 1 < NKT) {
            pa = *(const float4*)(aptr + (kt + 1) * 8);
            pb = *(const float4*)(bptr + (size_t)(kt + 1) * 8 * DIM);
        }
        #pragma unroll
        for (int k = 0; k < 8; k++) {
            float a[8], bb[8];
            *(float4*)&a[0]  = *(const float4*)&As[k * 128 + ty * 8];
            *(float4*)&a[4]  = *(const float4*)&As[k * 128 + ty * 8 + 4];
            *(float4*)&bb[0] = *(const float4*)&Bs[k * 128 + tx * 8];
            *(float4*)&bb[4] = *(const float4*)&Bs[k * 128 + tx * 8 + 4];
            #pragma unroll
            for (int i = 0; i < 8; i++)
                #pragma unroll
                for (int j = 0; j < 8; j++) acc[i][j] += a[i] * bb[j];
        }
        __syncthreads();
    }

    #pragma unroll
    for (int i = 0; i < 8; i++) {
        int r = m0 + ty * 8 + i;
        if (r < cnt) {
            float* cp = g_rbuf + (size_t)s_dst[ty * 8 + i] * DIM + n0 + tx * 8;
            *(float4*)(cp)     = make_float4(acc[i][0], acc[i][1], acc[i][2], acc[i][3]);
            *(float4*)(cp + 4) = make_float4(acc[i][4], acc[i][5], acc[i][6], acc[i][7]);
        }
    }
}

// ---------------- combine: out = shared + w0*slot0 + w1*slot1 ---------------
__global__ void combine_kernel(float* __restrict__ out) {
    int i4 = blockIdx.x * 256 + threadIdx.x;
    int t  = i4 >> 8;
    float w0 = g_top_w[2 * t], w1 = g_top_w[2 * t + 1];
    float4 a = ((const float4*)g_rbuf)[i4];
    float4 b = ((const float4*)g_rbuf)[(size_t)(N_TOK * DIM / 4) + i4];
    float4 c = ((const float4*)g_rbuf)[(size_t)(2 * N_TOK * DIM / 4) + i4];
    float4 o;
    o.x = c.x + w0 * a.x + w1 * b.x;
    o.y = c.y + w0 * a.y + w1 * b.y;
    o.z = c.z + w0 * a.z + w1 * b.z;
    o.w = c.w + w0 * a.w + w1 * b.w;
    ((float4*)out)[i4] = o;
}

// ---------------- launch ----------------------------------------------------
extern "C" void kernel_launch(void* const* d_in, const int* in_sizes, int n_in,
                              void* d_out, int out_size)
{
    const float* x  = (const float*)d_in[0];
    const float* sg = (const float*)d_in[1];
    const float* su = (const float*)d_in[2];
    const float* sd = (const float*)d_in[3];
    const float* Wg = (const float*)d_in[4];
    const float* Wu = (const float*)d_in[5];
    const float* Wd = (const float*)d_in[6];
    const float* Wr = (const float*)d_in[7];
    const float* lt = (const float*)d_in[8];
    const int*   li = (const int*)d_in[9];
    float* out = (float*)d_out;
    (void)in_sizes; (void)n_in; (void)out_size;

    zero_kernel<<<1, 32>>>();
    router_kernel<<<N_TOK / 8, 256>>>(x, Wr, lt, li);
    dispatch_kernel<<<N_TOK / 256, 256>>>();

    dim3 g1(16, N_TOK / 128, NSEG);
    gemm1_kernel<<<g1, 256>>>(x, Wg, Wu, sg, su);

    act_kernel<<<(NSEG * N_TOK * (HID / 4)) / 256, 256>>>();

    dim3 g2(8, N_TOK / 128, NSEG);
    gemm2_kernel<<<g2, 256>>>(Wd, sd);

    combine_kernel<<<(N_TOK * (DIM / 4)) / 256, 256>>>(out);
}

// round 3
// speedup vs baseline: 3.1987x; 3.1987x over previous
#include <cuda_runtime.h>
#include <cuda_bf16.h>
#include <cstdint>

#define N_TOK 4096
#define DIM   1024
#define HID   1024
#define NE    8
#define NSEG  9

// ---------------- scratch ---------------------------------------------------
__device__ int   g_cnt[NSEG];
__device__ int   g_assign_token[NE * N_TOK];
__device__ int   g_assign_slot [NE * N_TOK];
__device__ int   g_top_e[N_TOK * 2];
__device__ float g_top_w[N_TOK * 2];
__device__ __nv_bfloat16 g_Xh[(size_t)N_TOK * DIM];
__device__ __nv_bfloat16 g_Xl[(size_t)N_TOK * DIM];
// 27 matrices, K-major [k][n] (same layout as inputs): Wg[0..7], Wu[8..15], Wd[16..23], sg=24, su=25, sd=26
__device__ __nv_bfloat16 g_Wh[(size_t)27 * DIM * HID];
__device__ __nv_bfloat16 g_Wl[(size_t)27 * DIM * HID];
__device__ __nv_bfloat16 g_hh[(size_t)NSEG * N_TOK * HID];
__device__ __nv_bfloat16 g_hl[(size_t)NSEG * N_TOK * HID];
__device__ float g_rbuf[(size_t)3 * N_TOK * DIM];

// ---------------- helpers ---------------------------------------------------
__device__ __forceinline__ uint32_t smem_u32(const void* p) {
    uint32_t a;
    asm("{ .reg .u64 t; cvta.to.shared.u64 t, %1; cvt.u32.u64 %0, t; }"
        : "=r"(a) : "l"(p));
    return a;
}
#define CP_ASYNC16(dst, src) \
    asm volatile("cp.async.cg.shared.global [%0], [%1], 16;" :: "r"(dst), "l"(src))
#define CP_COMMIT() asm volatile("cp.async.commit_group;" ::: "memory")
#define CP_WAIT(n)  asm volatile("cp.async.wait_group %0;" :: "n"(n) : "memory")

__device__ __forceinline__ void ldsm_x4(uint32_t* r, uint32_t addr) {
    asm volatile("ldmatrix.sync.aligned.m8n8.x4.shared.b16 {%0,%1,%2,%3}, [%4];"
        : "=r"(r[0]), "=r"(r[1]), "=r"(r[2]), "=r"(r[3]) : "r"(addr));
}
__device__ __forceinline__ void ldsm_x2_t(uint32_t* r, uint32_t addr) {
    asm volatile("ldmatrix.sync.aligned.m8n8.x2.trans.shared.b16 {%0,%1}, [%2];"
        : "=r"(r[0]), "=r"(r[1]) : "r"(addr));
}
__device__ __forceinline__ void mma_bf16(float* d, const uint32_t* a, const uint32_t* b) {
    asm volatile(
        "mma.sync.aligned.m16n8k16.row.col.f32.bf16.bf16.f32 "
        "{%0,%1,%2,%3}, {%4,%5,%6,%7}, {%8,%9}, {%0,%1,%2,%3};"
        : "+f"(d[0]), "+f"(d[1]), "+f"(d[2]), "+f"(d[3])
        : "r"(a[0]), "r"(a[1]), "r"(a[2]), "r"(a[3]), "r"(b[0]), "r"(b[1]));
}
__device__ __forceinline__ float silu(float g) { return g / (1.f + __expf(-g)); }
__device__ __forceinline__ uint32_t pack_hi(float a, float b, float& ra, float& rb) {
    __nv_bfloat16 ha = __float2bfloat16(a), hb = __float2bfloat16(b);
    ra = a - __bfloat162float(ha);
    rb = b - __bfloat162float(hb);
    __nv_bfloat162 v; v.x = ha; v.y = hb;
    return *(uint32_t*)&v;
}
__device__ __forceinline__ uint32_t pack_lo(float a, float b) {
    __nv_bfloat162 v; v.x = __float2bfloat16(a); v.y = __float2bfloat16(b);
    return *(uint32_t*)&v;
}

// ---------------- small kernels ---------------------------------------------
__global__ void zero_kernel() {
    int t = threadIdx.x;
    if (t < NE) g_cnt[t] = 0;
    if (t == NE) g_cnt[NE] = N_TOK;
}

__global__ __launch_bounds__(256) void router_kernel(
    const float* __restrict__ X, const float* __restrict__ Wr,
    const float* __restrict__ loop_table, const int* __restrict__ loop_idx)
{
    __shared__ float s_bias[NE];
    const int warp = threadIdx.x >> 5, lane = threadIdx.x & 31;
    const float* le = loop_table + (size_t)loop_idx[0] * DIM;

    float b = 0.f;
    for (int d = lane; d < DIM; d += 32)
        b += le[d] * Wr[(size_t)(DIM + d) * NE + warp];
    #pragma unroll
    for (int o = 16; o; o >>= 1) b += __shfl_xor_sync(~0u, b, o);
    if (lane == 0) s_bias[warp] = b;
    __syncthreads();

    const int t = blockIdx.x * 8 + warp;
    const float* xr = X + (size_t)t * DIM;
    float acc[NE];
    #pragma unroll
    for (int e = 0; e < NE; e++) acc[e] = 0.f;
    for (int d = lane; d < DIM; d += 32) {
        float xv = xr[d];
        const float* wrow = Wr + (size_t)d * NE;
        #pragma unroll
        for (int e = 0; e < NE; e++) acc[e] += xv * wrow[e];
    }
    #pragma unroll
    for (int e = 0; e < NE; e++)
        #pragma unroll
        for (int o = 16; o; o >>= 1) acc[e] += __shfl_xor_sync(~0u, acc[e], o);

    if (lane == 0) {
        float p[NE];
        #pragma unroll
        for (int e = 0; e < NE; e++)
            p[e] = 1.f / (1.f + expf(-(acc[e] + s_bias[e])));
        int i0 = 0; float v0 = p[0];
        #pragma unroll
        for (int e = 1; e < NE; e++) if (p[e] > v0) { v0 = p[e]; i0 = e; }
        int i1 = -1; float v1 = -1e30f;
        #pragma unroll
        for (int e = 0; e < NE; e++) {
            if (e == i0) continue;
            if (p[e] > v1) { v1 = p[e]; i1 = e; }
        }
        g_top_e[t * 2 + 0] = i0;  g_top_e[t * 2 + 1] = i1;
        g_top_w[t * 2 + 0] = v0;  g_top_w[t * 2 + 1] = v1;
    }
}

__global__ void dispatch_kernel() {
    int t = blockIdx.x * blockDim.x + threadIdx.x;
    if (t >= N_TOK) return;
    #pragma unroll
    for (int k = 0; k < 2; k++) {
        int e = g_top_e[t * 2 + k];
        int pos = atomicAdd(&g_cnt[e], 1);
        g_assign_token[e * N_TOK + pos] = t;
        g_assign_slot [e * N_TOK + pos] = k;
    }
}

__global__ void convert_x_kernel(const float* __restrict__ x) {
    int i = blockIdx.x * 256 + threadIdx.x;
    float v = x[i];
    __nv_bfloat16 h = __float2bfloat16(v);
    g_Xh[i] = h;
    g_Xl[i] = __float2bfloat16(v - __bfloat162float(h));
}

// elementwise hi/lo split; layout stays [k][n]
__global__ void convert_w_kernel(
    const float* __restrict__ Wg, const float* __restrict__ Wu,
    const float* __restrict__ Wd, const float* __restrict__ sg,
    const float* __restrict__ su, const float* __restrict__ sd)
{
    int m = blockIdx.y;
    const float* src;
    if      (m < 8)  src = Wg + (size_t)m * DIM * HID;
    else if (m < 16) src = Wu + (size_t)(m - 8) * DIM * HID;
    else if (m < 24) src = Wd + (size_t)(m - 16) * DIM * HID;
    else if (m == 24) src = sg;
    else if (m == 25) src = su;
    else              src = sd;
    size_t i = (size_t)blockIdx.x * 256 + threadIdx.x;
    float v = src[i];
    size_t o = (size_t)m * DIM * HID + i;
    __nv_bfloat16 h = __float2bfloat16(v);
    g_Wh[o] = h;
    g_Wl[o] = __float2bfloat16(v - __bfloat162float(h));
}

// ---------------- GEMM1: X @ {Wg,Wu}[e], fused SiLU, bf16 hi/lo h out -------
// Block tile: 128 rows x (64 gate + 64 up) cols, BK=16, double-buffered cp.async.
// 8 warps as 2x4: warp = 64 rows x 16 cols (per matrix).
// smem pitches: A 48B/row (16 k-cols), B 144B/row (64 n-cols) -> ldmatrix conflict-free.
#define G1_AH  0u
#define G1_AL  6144u
#define G1_BGH 12288u
#define G1_BGL 14592u
#define G1_BUH 16896u
#define G1_BUL 19200u
#define G1_STG 21504u

__global__ __launch_bounds__(256) void gemm1_kernel() {
    __shared__ char sm[2 * G1_STG];
    __shared__ int  s_token[128];

    const int e   = blockIdx.z;
    const int cnt = g_cnt[e];
    const int m0  = blockIdx.y * 128;
    if (m0 >= cnt) return;
    const int n0  = blockIdx.x * 64;
    const int tid = threadIdx.x, wid = tid >> 5, lane = tid & 31;

    if (tid < 128) {
        int r = m0 + tid;
        s_token[tid] = (e < NE) ? ((r < cnt) ? g_assign_token[e * N_TOK + r] : 0) : r;
    }
    __syncthreads();
    const uint32_t sb = smem_u32(sm);

    const int ig = (e < NE) ? e : 24;
    const int iu = (e < NE) ? 8 + e : 25;
    const char* wgh = (const char*)(g_Wh + (size_t)ig * DIM * HID);
    const char* wgl = (const char*)(g_Wl + (size_t)ig * DIM * HID);
    const char* wuh = (const char*)(g_Wh + (size_t)iu * DIM * HID);
    const char* wul = (const char*)(g_Wl + (size_t)iu * DIM * HID);

    // per-thread loader roles
    const int ar = tid >> 1, ac = tid & 1;
    const char* aSrcH = (const char*)(g_Xh + (size_t)s_token[ar] * DIM) + ac * 16;
    const char* aSrcL = (const char*)(g_Xl + (size_t)s_token[ar] * DIM) + ac * 16;
    const uint32_t aDstH = sb + G1_AH + ar * 48 + ac * 16;
    const uint32_t aDstL = sb + G1_AL + ar * 48 + ac * 16;
    const int brow = (tid & 127) >> 3, bc = (tid & 7) * 16;
    const bool hi = tid < 128;
    const char* bSrcG = (hi ? wgh : wgl) + (size_t)brow * HID * 2 + n0 * 2 + bc;
    const char* bSrcU = (hi ? wuh : wul) + (size_t)brow * HID * 2 + n0 * 2 + bc;
    const uint32_t bDstG = sb + (hi ? G1_BGH : G1_BGL) + brow * 144 + bc;
    const uint32_t bDstU = sb + (hi ? G1_BUH : G1_BUL) + brow * 144 + bc;

#define G1_LOAD(k0, buf) do { \
        uint32_t _o = (buf) * G1_STG; \
        size_t _bk = (size_t)(k0) * HID * 2; \
        CP_ASYNC16(aDstH + _o, aSrcH + (k0) * 2); \
        CP_ASYNC16(aDstL + _o, aSrcL + (k0) * 2); \
        CP_ASYNC16(bDstG + _o, bSrcG + _bk); \
        CP_ASYNC16(bDstU + _o, bSrcU + _bk); \
        CP_COMMIT(); } while (0)

    // compute addressing
    const int wm = (wid >> 2) * 64, wn = (wid & 3) * 16;
    const int am = (lane & 7) + ((lane >> 3) & 1) * 8;
    const uint32_t ako = (lane >> 4) * 16;
    const uint32_t aBH = sb + G1_AH + (wm + am) * 48 + ako;
    const uint32_t aBL = sb + G1_AL + (wm + am) * 48 + ako;
    const int bk = lane & 15;
    const uint32_t bGH = sb + G1_BGH + bk * 144 + wn * 2;
    const uint32_t bGL = sb + G1_BGL + bk * 144 + wn * 2;
    const uint32_t bUH = sb + G1_BUH + bk * 144 + wn * 2;
    const uint32_t bUL = sb + G1_BUL + bk * 144 + wn * 2;

    float accG[4][2][4], accU[4][2][4];
    #pragma unroll
    for (int i = 0; i < 4; i++)
        #pragma unroll
        for (int j = 0; j < 2; j++)
            #pragma unroll
            for (int q = 0; q < 4; q++) { accG[i][j][q] = 0.f; accU[i][j][q] = 0.f; }

    G1_LOAD(0, 0);
    G1_LOAD(16, 1);
    CP_WAIT(1); __syncthreads();

    for (int s = 0; s < 64; s++) {
        const int buf = s & 1;
        const uint32_t off = buf * G1_STG;

        uint32_t ah[4][4], al[4][4], bgh[2][2], bgl[2][2], buh[2][2], bul[2][2];
        #pragma unroll
        for (int i = 0; i < 4; i++) {
            ldsm_x4(ah[i], aBH + off + i * 768);
            ldsm_x4(al[i], aBL + off + i * 768);
        }
        #pragma unroll
        for (int j = 0; j < 2; j++) {
            ldsm_x2_t(bgh[j], bGH + off + j * 16);
            ldsm_x2_t(bgl[j], bGL + off + j * 16);
            ldsm_x2_t(buh[j], bUH + off + j * 16);
            ldsm_x2_t(bul[j], bUL + off + j * 16);
        }
        #pragma unroll
        for (int i = 0; i < 4; i++)
            #pragma unroll
            for (int j = 0; j < 2; j++) {
                mma_bf16(accG[i][j], ah[i], bgh[j]);
                mma_bf16(accG[i][j], ah[i], bgl[j]);
                mma_bf16(accG[i][j], al[i], bgh[j]);
                mma_bf16(accU[i][j], ah[i], buh[j]);
                mma_bf16(accU[i][j], ah[i], bul[j]);
                mma_bf16(accU[i][j], al[i], buh[j]);
            }
        __syncthreads();
        if (s + 2 < 64) { G1_LOAD((s + 2) * 16, buf); CP_WAIT(1); }
        else            { CP_WAIT(0); }
        __syncthreads();
    }

    // epilogue: h = silu(gate)*up, split hi/lo bf16
    const int q = lane >> 2, r4 = lane & 3;
    #pragma unroll
    for (int i = 0; i < 4; i++) {
        const int lr0 = wm + i * 16 + q, lr1 = lr0 + 8;
        const bool ok0 = (m0 + lr0) < cnt, ok1 = (m0 + lr1) < cnt;
        const size_t b0 = ((size_t)e * N_TOK + m0 + lr0) * HID + n0;
        const size_t b1 = ((size_t)e * N_TOK + m0 + lr1) * HID + n0;
        #pragma unroll
        for (int j = 0; j < 2; j++) {
            const int col = wn + j * 8 + r4 * 2;
            float h00 = silu(accG[i][j][0]) * accU[i][j][0];
            float h01 = silu(accG[i][j][1]) * accU[i][j][1];
            float h10 = silu(accG[i][j][2]) * accU[i][j][2];
            float h11 = silu(accG[i][j][3]) * accU[i][j][3];
            float r00, r01, r10, r11;
            uint32_t p0 = pack_hi(h00, h01, r00, r01);
            uint32_t p1 = pack_hi(h10, h11, r10, r11);
            if (ok0) {
                *(uint32_t*)(g_hh + b0 + col) = p0;
                *(uint32_t*)(g_hl + b0 + col) = pack_lo(r00, r01);
            }
            if (ok1) {
                *(uint32_t*)(g_hh + b1 + col) = p1;
                *(uint32_t*)(g_hl + b1 + col) = pack_lo(r10, r11);
            }
        }
    }
#undef G1_LOAD
}

// ---------------- GEMM2: h @ Wd[e] -> scattered fp32 rbuf -------------------
// Block tile: 128 x 128, BK=16. 8 warps as 2x4: warp = 64 x 32.
#define G2_AH 0u
#define G2_AL 6144u
#define G2_BH 12288u
#define G2_BL 16640u
#define G2_STG 20992u

__global__ __launch_bounds__(256) void gemm2_kernel() {
    __shared__ char sm[2 * G2_STG];
    __shared__ int  s_dst[128];

    const int e   = blockIdx.z;
    const int cnt = g_cnt[e];
    const int m0  = blockIdx.y * 128;
    if (m0 >= cnt) return;
    const int n0  = blockIdx.x * 128;
    const int tid = threadIdx.x, wid = tid >> 5, lane = tid & 31;

    if (tid < 128) {
        int r = m0 + tid, dst = 0;
        if (r < cnt) {
            if (e < NE)
                dst = g_assign_slot[e * N_TOK + r] * N_TOK + g_assign_token[e * N_TOK + r];
            else
                dst = 2 * N_TOK + r;
        }
        s_dst[tid] = dst;
    }
    __syncthreads();
    const uint32_t sb = smem_u32(sm);

    const int id = (e < NE) ? 16 + e : 26;
    const char* wdh = (const char*)(g_Wh + (size_t)id * DIM * HID);
    const char* wdl = (const char*)(g_Wl + (size_t)id * DIM * HID);

    const int ar = tid >> 1, ac = tid & 1;
    const char* aSrcH = (const char*)(g_hh + ((size_t)e * N_TOK + m0 + ar) * HID) + ac * 16;
    const char* aSrcL = (const char*)(g_hl + ((size_t)e * N_TOK + m0 + ar) * HID) + ac * 16;
    const uint32_t aDstH = sb + G2_AH + ar * 48 + ac * 16;
    const uint32_t aDstL = sb + G2_AL + ar * 48 + ac * 16;
    const int brow = tid >> 4, bc = (tid & 15) * 16;
    const char* bSrcH = wdh + (size_t)brow * DIM * 2 + n0 * 2 + bc;
    const char* bSrcL = wdl + (size_t)brow * DIM * 2 + n0 * 2 + bc;
    const uint32_t bDstH = sb + G2_BH + brow * 272 + bc;
    const uint32_t bDstL = sb + G2_BL + brow * 272 + bc;

#define G2_LOAD(k0, buf) do { \
        uint32_t _o = (buf) * G2_STG; \
        size_t _bk = (size_t)(k0) * DIM * 2; \
        CP_ASYNC16(aDstH + _o, aSrcH + (k0) * 2); \
        CP_ASYNC16(aDstL + _o, aSrcL + (k0) * 2); \
        CP_ASYNC16(bDstH + _o, bSrcH + _bk); \
        CP_ASYNC16(bDstL + _o, bSrcL + _bk); \
        CP_COMMIT(); } while (0)

    const int wm = (wid >> 2) * 64, wn = (wid & 3) * 32;
    const int am = (lane & 7) + ((lane >> 3) & 1) * 8;
    const uint32_t ako = (lane >> 4) * 16;
    const uint32_t aBH = sb + G2_AH + (wm + am) * 48 + ako;
    const uint32_t aBL = sb + G2_AL + (wm + am) * 48 + ako;
    const int bkr = lane & 15;
    const uint32_t bBH = sb + G2_BH + bkr * 272 + wn * 2;
    const uint32_t bBL = sb + G2_BL + bkr * 272 + wn * 2;

    float acc[4][4][4];
    #pragma unroll
    for (int i = 0; i < 4; i++)
        #pragma unroll
        for (int j = 0; j < 4; j++)
            #pragma unroll
            for (int q = 0; q < 4; q++) acc[i][j][q] = 0.f;

    G2_LOAD(0, 0);
    G2_LOAD(16, 1);
    CP_WAIT(1); __syncthreads();

    for (int s = 0; s < 64; s++) {
        const int buf = s & 1;
        const uint32_t off = buf * G2_STG;

        uint32_t ah[4][4], al[4][4], bh[4][2], bl[4][2];
        #pragma unroll
        for (int i = 0; i < 4; i++) {
            ldsm_x4(ah[i], aBH + off + i * 768);
            ldsm_x4(al[i], aBL + off + i * 768);
        }
        #pragma unroll
        for (int j = 0; j < 4; j++) {
            ldsm_x2_t(bh[j], bBH + off + j * 16);
            ldsm_x2_t(bl[j], bBL + off + j * 16);
        }
        #pragma unroll
        for (int i = 0; i < 4; i++)
            #pragma unroll
            for (int j = 0; j < 4; j++) {
                mma_bf16(acc[i][j], ah[i], bh[j]);
                mma_bf16(acc[i][j], ah[i], bl[j]);
                mma_bf16(acc[i][j], al[i], bh[j]);
            }
        __syncthreads();
        if (s + 2 < 64) { G2_LOAD((s + 2) * 16, buf); CP_WAIT(1); }
        else            { CP_WAIT(0); }
        __syncthreads();
    }

    const int q = lane >> 2, r4 = lane & 3;
    #pragma unroll
    for (int i = 0; i < 4; i++) {
        const int lr0 = wm + i * 16 + q, lr1 = lr0 + 8;
        const bool ok0 = (m0 + lr0) < cnt, ok1 = (m0 + lr1) < cnt;
        float* d0 = g_rbuf + (size_t)s_dst[lr0] * DIM + n0;
        float* d1 = g_rbuf + (size_t)s_dst[lr1] * DIM + n0;
        #pragma unroll
        for (int j = 0; j < 4; j++) {
            const int col = wn + j * 8 + r4 * 2;
            if (ok0) *(float2*)(d0 + col) = make_float2(acc[i][j][0], acc[i][j][1]);
            if (ok1) *(float2*)(d1 + col) = make_float2(acc[i][j][2], acc[i][j][3]);
        }
    }
#undef G2_LOAD
}

// ---------------- combine ---------------------------------------------------
__global__ void combine_kernel(float* __restrict__ out) {
    int i4 = blockIdx.x * 256 + threadIdx.x;
    int t  = i4 >> 8;
    float w0 = g_top_w[2 * t], w1 = g_top_w[2 * t + 1];
    float4 a = ((const float4*)g_rbuf)[i4];
    float4 b = ((const float4*)g_rbuf)[(size_t)(N_TOK * DIM / 4) + i4];
    float4 c = ((const float4*)g_rbuf)[(size_t)(2 * N_TOK * DIM / 4) + i4];
    float4 o;
    o.x = c.x + w0 * a.x + w1 * b.x;
    o.y = c.y + w0 * a.y + w1 * b.y;
    o.z = c.z + w0 * a.z + w1 * b.z;
    o.w = c.w + w0 * a.w + w1 * b.w;
    ((float4*)out)[i4] = o;
}

// ---------------- launch ----------------------------------------------------
extern "C" void kernel_launch(void* const* d_in, const int* in_sizes, int n_in,
                              void* d_out, int out_size)
{
    const float* x  = (const float*)d_in[0];
    const float* sg = (const float*)d_in[1];
    const float* su = (const float*)d_in[2];
    const float* sd = (const float*)d_in[3];
    const float* Wg = (const float*)d_in[4];
    const float* Wu = (const float*)d_in[5];
    const float* Wd = (const float*)d_in[6];
    const float* Wr = (const float*)d_in[7];
    const float* lt = (const float*)d_in[8];
    const int*   li = (const int*)d_in[9];
    float* out = (float*)d_out;
    (void)in_sizes; (void)n_in; (void)out_size;

    zero_kernel<<<1, 32>>>();
    convert_x_kernel<<<(N_TOK * DIM) / 256, 256>>>(x);
    convert_w_kernel<<<dim3((DIM * HID) / 256, 27), 256>>>(Wg, Wu, Wd, sg, su, sd);
    router_kernel<<<N_TOK / 8, 256>>>(x, Wr, lt, li);
    dispatch_kernel<<<N_TOK / 256, 256>>>();

    gemm1_kernel<<<dim3(HID / 64, N_TOK / 128, NSEG), 256>>>();
    gemm2_kernel<<<dim3(DIM / 128, N_TOK / 128, NSEG), 256>>>();
    combine_kernel<<<(N_TOK * (DIM / 4)) / 256, 256>>>(out);
}

// round 4
// speedup vs baseline: 3.2327x; 1.0106x over previous
#include <cuda_runtime.h>
#include <cuda_bf16.h>
#include <cstdint>

#define N_TOK 4096
#define DIM   1024
#define HID   1024
#define NE    8
#define NSEG  9

// ---------------- scratch ---------------------------------------------------
__device__ int   g_cnt[NSEG];
__device__ int   g_assign_token[NE * N_TOK];
__device__ int   g_assign_slot [NE * N_TOK];
__device__ int   g_top_e[N_TOK * 2];
__device__ float g_top_w[N_TOK * 2];
__device__ __nv_bfloat16 g_Xh[(size_t)N_TOK * DIM];
__device__ __nv_bfloat16 g_Xl[(size_t)N_TOK * DIM];
// 27 matrices, K-major [k][n]: Wg[0..7], Wu[8..15], Wd[16..23], sg=24, su=25, sd=26
__device__ __nv_bfloat16 g_Wh[(size_t)27 * DIM * HID];
__device__ __nv_bfloat16 g_Wl[(size_t)27 * DIM * HID];
__device__ __nv_bfloat16 g_hh[(size_t)NSEG * N_TOK * HID];
__device__ __nv_bfloat16 g_hl[(size_t)NSEG * N_TOK * HID];
__device__ float g_rbuf[(size_t)3 * N_TOK * DIM];

// ---------------- helpers ---------------------------------------------------
__device__ __forceinline__ uint32_t smem_u32(const void* p) {
    uint32_t a;
    asm("{ .reg .u64 t; cvta.to.shared.u64 t, %1; cvt.u32.u64 %0, t; }"
        : "=r"(a) : "l"(p));
    return a;
}
#define CP_ASYNC16(dst, src) \
    asm volatile("cp.async.cg.shared.global [%0], [%1], 16;" :: "r"(dst), "l"(src))
#define CP_COMMIT() asm volatile("cp.async.commit_group;" ::: "memory")
#define CP_WAIT(n)  asm volatile("cp.async.wait_group %0;" :: "n"(n) : "memory")

__device__ __forceinline__ void ldsm_x4(uint32_t* r, uint32_t addr) {
    asm volatile("ldmatrix.sync.aligned.m8n8.x4.shared.b16 {%0,%1,%2,%3}, [%4];"
        : "=r"(r[0]), "=r"(r[1]), "=r"(r[2]), "=r"(r[3]) : "r"(addr));
}
__device__ __forceinline__ void ldsm_x2_t(uint32_t* r, uint32_t addr) {
    asm volatile("ldmatrix.sync.aligned.m8n8.x2.trans.shared.b16 {%0,%1}, [%2];"
        : "=r"(r[0]), "=r"(r[1]) : "r"(addr));
}
__device__ __forceinline__ void mma_bf16(float* d, const uint32_t* a, const uint32_t* b) {
    asm volatile(
        "mma.sync.aligned.m16n8k16.row.col.f32.bf16.bf16.f32 "
        "{%0,%1,%2,%3}, {%4,%5,%6,%7}, {%8,%9}, {%0,%1,%2,%3};"
        : "+f"(d[0]), "+f"(d[1]), "+f"(d[2]), "+f"(d[3])
        : "r"(a[0]), "r"(a[1]), "r"(a[2]), "r"(a[3]), "r"(b[0]), "r"(b[1]));
}
__device__ __forceinline__ float silu(float g) { return g / (1.f + __expf(-g)); }
__device__ __forceinline__ uint32_t pack_hi(float a, float b, float& ra, float& rb) {
    __nv_bfloat16 ha = __float2bfloat16(a), hb = __float2bfloat16(b);
    ra = a - __bfloat162float(ha);
    rb = b - __bfloat162float(hb);
    __nv_bfloat162 v; v.x = ha; v.y = hb;
    return *(uint32_t*)&v;
}
__device__ __forceinline__ uint32_t pack_lo(float a, float b) {
    __nv_bfloat162 v; v.x = __float2bfloat16(a); v.y = __float2bfloat16(b);
    return *(uint32_t*)&v;
}

// ---------------- small kernels ---------------------------------------------
__global__ void zero_kernel() {
    int t = threadIdx.x;
    if (t < NE) g_cnt[t] = 0;
    if (t == NE) g_cnt[NE] = N_TOK;
}

// router: Wr x-part cached transposed in smem; 32 tokens/block, 4 per warp.
__global__ __launch_bounds__(256) void router_kernel(
    const float* __restrict__ X, const float* __restrict__ Wr,
    const float* __restrict__ loop_table, const int* __restrict__ loop_idx)
{
    __shared__ float4 sW[NE][256];   // [e][k4] transposed, 32KB
    __shared__ float s_bias[NE];
    const int tid = threadIdx.x, warp = tid >> 5, lane = tid & 31;

    for (int i = tid; i < NE * 256; i += 256) {
        int e = i >> 8, k4 = i & 255;
        sW[e][k4] = make_float4(Wr[(size_t)(k4 * 4 + 0) * NE + e],
                                Wr[(size_t)(k4 * 4 + 1) * NE + e],
                                Wr[(size_t)(k4 * 4 + 2) * NE + e],
                                Wr[(size_t)(k4 * 4 + 3) * NE + e]);
    }
    const float* le = loop_table + (size_t)loop_idx[0] * DIM;
    float b = 0.f;
    for (int d = lane; d < DIM; d += 32)
        b += le[d] * Wr[(size_t)(DIM + d) * NE + warp];
    #pragma unroll
    for (int o = 16; o; o >>= 1) b += __shfl_xor_sync(~0u, b, o);
    if (lane == 0) s_bias[warp] = b;
    __syncthreads();

    #pragma unroll
    for (int rep = 0; rep < 4; rep++) {
        const int t = blockIdx.x * 32 + warp * 4 + rep;
        const float4* xr = (const float4*)(X + (size_t)t * DIM);
        float acc[NE];
        #pragma unroll
        for (int e = 0; e < NE; e++) acc[e] = 0.f;
        #pragma unroll
        for (int i = 0; i < 8; i++) {
            float4 xv = xr[lane + 32 * i];
            #pragma unroll
            for (int e = 0; e < NE; e++) {
                float4 w = sW[e][lane + 32 * i];
                acc[e] += xv.x * w.x + xv.y * w.y + xv.z * w.z + xv.w * w.w;
            }
        }
        #pragma unroll
        for (int e = 0; e < NE; e++)
            #pragma unroll
            for (int o = 16; o; o >>= 1) acc[e] += __shfl_xor_sync(~0u, acc[e], o);

        if (lane == 0) {
            float p[NE];
            #pragma unroll
            for (int e = 0; e < NE; e++)
                p[e] = 1.f / (1.f + expf(-(acc[e] + s_bias[e])));
            int i0 = 0; float v0 = p[0];
            #pragma unroll
            for (int e = 1; e < NE; e++) if (p[e] > v0) { v0 = p[e]; i0 = e; }
            int i1 = -1; float v1 = -1e30f;
            #pragma unroll
            for (int e = 0; e < NE; e++) {
                if (e == i0) continue;
                if (p[e] > v1) { v1 = p[e]; i1 = e; }
            }
            g_top_e[t * 2 + 0] = i0;  g_top_e[t * 2 + 1] = i1;
            g_top_w[t * 2 + 0] = v0;  g_top_w[t * 2 + 1] = v1;
        }
    }
}

__global__ void dispatch_kernel() {
    int t = blockIdx.x * blockDim.x + threadIdx.x;
    if (t >= N_TOK) return;
    #pragma unroll
    for (int k = 0; k < 2; k++) {
        int e = g_top_e[t * 2 + k];
        int pos = atomicAdd(&g_cnt[e], 1);
        g_assign_token[e * N_TOK + pos] = t;
        g_assign_slot [e * N_TOK + pos] = k;
    }
}

__global__ void convert_x_kernel(const float* __restrict__ x) {
    size_t i4 = (size_t)blockIdx.x * 256 + threadIdx.x;
    float4 v = ((const float4*)x)[i4];
    __nv_bfloat16 h0 = __float2bfloat16(v.x), h1 = __float2bfloat16(v.y);
    __nv_bfloat16 h2 = __float2bfloat16(v.z), h3 = __float2bfloat16(v.w);
    __nv_bfloat162 a, bq, c, d;
    a.x = h0; a.y = h1; bq.x = h2; bq.y = h3;
    c.x = __float2bfloat16(v.x - __bfloat162float(h0));
    c.y = __float2bfloat16(v.y - __bfloat162float(h1));
    d.x = __float2bfloat16(v.z - __bfloat162float(h2));
    d.y = __float2bfloat16(v.w - __bfloat162float(h3));
    uint2 hv = make_uint2(*(uint32_t*)&a, *(uint32_t*)&bq);
    uint2 lv = make_uint2(*(uint32_t*)&c, *(uint32_t*)&d);
    ((uint2*)g_Xh)[i4] = hv;
    ((uint2*)g_Xl)[i4] = lv;
}

__global__ void convert_w_kernel(
    const float* __restrict__ Wg, const float* __restrict__ Wu,
    const float* __restrict__ Wd, const float* __restrict__ sg,
    const float* __restrict__ su, const float* __restrict__ sd)
{
    int m = blockIdx.y;
    const float* src;
    if      (m < 8)  src = Wg + (size_t)m * DIM * HID;
    else if (m < 16) src = Wu + (size_t)(m - 8) * DIM * HID;
    else if (m < 24) src = Wd + (size_t)(m - 16) * DIM * HID;
    else if (m == 24) src = sg;
    else if (m == 25) src = su;
    else              src = sd;
    size_t i4 = (size_t)blockIdx.x * 256 + threadIdx.x;
    float4 v = ((const float4*)src)[i4];
    __nv_bfloat16 h0 = __float2bfloat16(v.x), h1 = __float2bfloat16(v.y);
    __nv_bfloat16 h2 = __float2bfloat16(v.z), h3 = __float2bfloat16(v.w);
    __nv_bfloat162 a, bq, c, d;
    a.x = h0; a.y = h1; bq.x = h2; bq.y = h3;
    c.x = __float2bfloat16(v.x - __bfloat162float(h0));
    c.y = __float2bfloat16(v.y - __bfloat162float(h1));
    d.x = __float2bfloat16(v.z - __bfloat162float(h2));
    d.y = __float2bfloat16(v.w - __bfloat162float(h3));
    size_t o = (size_t)m * (DIM * HID / 4) + i4;
    ((uint2*)g_Wh)[o] = make_uint2(*(uint32_t*)&a, *(uint32_t*)&bq);
    ((uint2*)g_Wl)[o] = make_uint2(*(uint32_t*)&c, *(uint32_t*)&d);
}

// ---------------- GEMM1: X @ {Wg,Wu}[e], fused SiLU, bf16 hi/lo h out -------
// Block 128 x (64g + 64u), BK=16, 3-stage cp.async pipeline.
#define G1_AH  0u
#define G1_AL  6144u
#define G1_BGH 12288u
#define G1_BGL 14592u
#define G1_BUH 16896u
#define G1_BUL 19200u
#define G1_STG 21504u

__global__ __launch_bounds__(256) void gemm1_kernel() {
    extern __shared__ char sm[];
    __shared__ int s_token[128];

    const int e   = blockIdx.z;
    const int cnt = g_cnt[e];
    const int m0  = blockIdx.y * 128;
    if (m0 >= cnt) return;
    const int n0  = blockIdx.x * 64;
    const int tid = threadIdx.x, wid = tid >> 5, lane = tid & 31;

    if (tid < 128) {
        int r = m0 + tid;
        s_token[tid] = (e < NE) ? ((r < cnt) ? g_assign_token[e * N_TOK + r] : 0) : r;
    }
    __syncthreads();
    const uint32_t sb = smem_u32(sm);

    const int ig = (e < NE) ? e : 24;
    const int iu = (e < NE) ? 8 + e : 25;
    const char* wgh = (const char*)(g_Wh + (size_t)ig * DIM * HID);
    const char* wgl = (const char*)(g_Wl + (size_t)ig * DIM * HID);
    const char* wuh = (const char*)(g_Wh + (size_t)iu * DIM * HID);
    const char* wul = (const char*)(g_Wl + (size_t)iu * DIM * HID);

    const int ar = tid >> 1, ac = tid & 1;
    const char* aSrcH = (const char*)(g_Xh + (size_t)s_token[ar] * DIM) + ac * 16;
    const char* aSrcL = (const char*)(g_Xl + (size_t)s_token[ar] * DIM) + ac * 16;
    const uint32_t aDstH = sb + G1_AH + ar * 48 + ac * 16;
    const uint32_t aDstL = sb + G1_AL + ar * 48 + ac * 16;
    const int brow = (tid & 127) >> 3, bc = (tid & 7) * 16;
    const bool hi = tid < 128;
    const char* bSrcG = (hi ? wgh : wgl) + (size_t)brow * HID * 2 + n0 * 2 + bc;
    const char* bSrcU = (hi ? wuh : wul) + (size_t)brow * HID * 2 + n0 * 2 + bc;
    const uint32_t bDstG = sb + (hi ? G1_BGH : G1_BGL) + brow * 144 + bc;
    const uint32_t bDstU = sb + (hi ? G1_BUH : G1_BUL) + brow * 144 + bc;

#define G1_LOAD(k0, buf) do { \
        uint32_t _o = (uint32_t)(buf) * G1_STG; \
        size_t _bk = (size_t)(k0) * HID * 2; \
        CP_ASYNC16(aDstH + _o, aSrcH + (size_t)(k0) * 2); \
        CP_ASYNC16(aDstL + _o, aSrcL + (size_t)(k0) * 2); \
        CP_ASYNC16(bDstG + _o, bSrcG + _bk); \
        CP_ASYNC16(bDstU + _o, bSrcU + _bk); \
        CP_COMMIT(); } while (0)

    const int wm = (wid >> 2) * 64, wn = (wid & 3) * 16;
    const int am = (lane & 7) + ((lane >> 3) & 1) * 8;
    const uint32_t ako = (lane >> 4) * 16;
    const uint32_t aBH = sb + G1_AH + (wm + am) * 48 + ako;
    const uint32_t aBL = sb + G1_AL + (wm + am) * 48 + ako;
    const int bk = lane & 15;
    const uint32_t bGH = sb + G1_BGH + bk * 144 + wn * 2;
    const uint32_t bGL = sb + G1_BGL + bk * 144 + wn * 2;
    const uint32_t bUH = sb + G1_BUH + bk * 144 + wn * 2;
    const uint32_t bUL = sb + G1_BUL + bk * 144 + wn * 2;

    float accG[4][2][4], accU[4][2][4];
    #pragma unroll
    for (int i = 0; i < 4; i++)
        #pragma unroll
        for (int j = 0; j < 2; j++)
            #pragma unroll
            for (int q = 0; q < 4; q++) { accG[i][j][q] = 0.f; accU[i][j][q] = 0.f; }

    G1_LOAD(0, 0);
    G1_LOAD(16, 1);
    CP_WAIT(1); __syncthreads();

    int cur = 0;
    for (int s = 0; s < 64; s++) {
        int ldb = cur + 2; if (ldb >= 3) ldb -= 3;
        if (s + 2 < 64) G1_LOAD((s + 2) * 16, ldb);

        const uint32_t off = (uint32_t)cur * G1_STG;
        uint32_t ah[4][4], al[4][4], bgh[2][2], bgl[2][2], buh[2][2], bul[2][2];
        #pragma unroll
        for (int i = 0; i < 4; i++) {
            ldsm_x4(ah[i], aBH + off + i * 768);
            ldsm_x4(al[i], aBL + off + i * 768);
        }
        #pragma unroll
        for (int j = 0; j < 2; j++) {
            ldsm_x2_t(bgh[j], bGH + off + j * 16);
            ldsm_x2_t(bgl[j], bGL + off + j * 16);
            ldsm_x2_t(buh[j], bUH + off + j * 16);
            ldsm_x2_t(bul[j], bUL + off + j * 16);
        }
        #pragma unroll
        for (int i = 0; i < 4; i++)
            #pragma unroll
            for (int j = 0; j < 2; j++) {
                mma_bf16(accG[i][j], ah[i], bgh[j]);
                mma_bf16(accG[i][j], ah[i], bgl[j]);
                mma_bf16(accG[i][j], al[i], bgh[j]);
                mma_bf16(accU[i][j], ah[i], buh[j]);
                mma_bf16(accU[i][j], ah[i], bul[j]);
                mma_bf16(accU[i][j], al[i], buh[j]);
            }
        if (s + 2 < 64) CP_WAIT(1); else CP_WAIT(0);
        __syncthreads();
        cur++; if (cur == 3) cur = 0;
    }

    const int q = lane >> 2, r4 = lane & 3;
    #pragma unroll
    for (int i = 0; i < 4; i++) {
        const int lr0 = wm + i * 16 + q, lr1 = lr0 + 8;
        const bool ok0 = (m0 + lr0) < cnt, ok1 = (m0 + lr1) < cnt;
        const size_t b0 = ((size_t)e * N_TOK + m0 + lr0) * HID + n0;
        const size_t b1 = ((size_t)e * N_TOK + m0 + lr1) * HID + n0;
        #pragma unroll
        for (int j = 0; j < 2; j++) {
            const int col = wn + j * 8 + r4 * 2;
            float h00 = silu(accG[i][j][0]) * accU[i][j][0];
            float h01 = silu(accG[i][j][1]) * accU[i][j][1];
            float h10 = silu(accG[i][j][2]) * accU[i][j][2];
            float h11 = silu(accG[i][j][3]) * accU[i][j][3];
            float r00, r01, r10, r11;
            uint32_t p0 = pack_hi(h00, h01, r00, r01);
            uint32_t p1 = pack_hi(h10, h11, r10, r11);
            if (ok0) {
                *(uint32_t*)(g_hh + b0 + col) = p0;
                *(uint32_t*)(g_hl + b0 + col) = pack_lo(r00, r01);
            }
            if (ok1) {
                *(uint32_t*)(g_hh + b1 + col) = p1;
                *(uint32_t*)(g_hl + b1 + col) = pack_lo(r10, r11);
            }
        }
    }
#undef G1_LOAD
}

// ---------------- GEMM2: h @ Wd[e] -> scattered fp32 rbuf -------------------
#define G2_AH 0u
#define G2_AL 6144u
#define G2_BH 12288u
#define G2_BL 16640u
#define G2_STG 20992u

__global__ __launch_bounds__(256) void gemm2_kernel() {
    extern __shared__ char sm[];
    __shared__ int s_dst[128];

    const int e   = blockIdx.z;
    const int cnt = g_cnt[e];
    const int m0  = blockIdx.y * 128;
    if (m0 >= cnt) return;
    const int n0  = blockIdx.x * 128;
    const int tid = threadIdx.x, wid = tid >> 5, lane = tid & 31;

    if (tid < 128) {
        int r = m0 + tid, dst = 0;
        if (r < cnt) {
            if (e < NE)
                dst = g_assign_slot[e * N_TOK + r] * N_TOK + g_assign_token[e * N_TOK + r];
            else
                dst = 2 * N_TOK + r;
        }
        s_dst[tid] = dst;
    }
    __syncthreads();
    const uint32_t sb = smem_u32(sm);

    const int id = (e < NE) ? 16 + e : 26;
    const char* wdh = (const char*)(g_Wh + (size_t)id * DIM * HID);
    const char* wdl = (const char*)(g_Wl + (size_t)id * DIM * HID);

    const int ar = tid >> 1, ac = tid & 1;
    const char* aSrcH = (const char*)(g_hh + ((size_t)e * N_TOK + m0 + ar) * HID) + ac * 16;
    const char* aSrcL = (const char*)(g_hl + ((size_t)e * N_TOK + m0 + ar) * HID) + ac * 16;
    const uint32_t aDstH = sb + G2_AH + ar * 48 + ac * 16;
    const uint32_t aDstL = sb + G2_AL + ar * 48 + ac * 16;
    const int brow = tid >> 4, bc = (tid & 15) * 16;
    const char* bSrcH = wdh + (size_t)brow * DIM * 2 + n0 * 2 + bc;
    const char* bSrcL = wdl + (size_t)brow * DIM * 2 + n0 * 2 + bc;
    const uint32_t bDstH = sb + G2_BH + brow * 272 + bc;
    const uint32_t bDstL = sb + G2_BL + brow * 272 + bc;

#define G2_LOAD(k0, buf) do { \
        uint32_t _o = (uint32_t)(buf) * G2_STG; \
        size_t _bk = (size_t)(k0) * DIM * 2; \
        CP_ASYNC16(aDstH + _o, aSrcH + (size_t)(k0) * 2); \
        CP_ASYNC16(aDstL + _o, aSrcL + (size_t)(k0) * 2); \
        CP_ASYNC16(bDstH + _o, bSrcH + _bk); \
        CP_ASYNC16(bDstL + _o, bSrcL + _bk); \
        CP_COMMIT(); } while (0)

    const int wm = (wid >> 2) * 64, wn = (wid & 3) * 32;
    const int am = (lane & 7) + ((lane >> 3) & 1) * 8;
    const uint32_t ako = (lane >> 4) * 16;
    const uint32_t aBH = sb + G2_AH + (wm + am) * 48 + ako;
    const uint32_t aBL = sb + G2_AL + (wm + am) * 48 + ako;
    const int bkr = lane & 15;
    const uint32_t bBH = sb + G2_BH + bkr * 272 + wn * 2;
    const uint32_t bBL = sb + G2_BL + bkr * 272 + wn * 2;

    float acc[4][4][4];
    #pragma unroll
    for (int i = 0; i < 4; i++)
        #pragma unroll
        for (int j = 0; j < 4; j++)
            #pragma unroll
            for (int q = 0; q < 4; q++) acc[i][j][q] = 0.f;

    G2_LOAD(0, 0);
    G2_LOAD(16, 1);
    CP_WAIT(1); __syncthreads();

    int cur = 0;
    for (int s = 0; s < 64; s++) {
        int ldb = cur + 2; if (ldb >= 3) ldb -= 3;
        if (s + 2 < 64) G2_LOAD((s + 2) * 16, ldb);

        const uint32_t off = (uint32_t)cur * G2_STG;
        uint32_t ah[4][4], al[4][4], bh[4][2], bl[4][2];
        #pragma unroll
        for (int i = 0; i < 4; i++) {
            ldsm_x4(ah[i], aBH + off + i * 768);
            ldsm_x4(al[i], aBL + off + i * 768);
        }
        #pragma unroll
        for (int j = 0; j < 4; j++) {
            ldsm_x2_t(bh[j], bBH + off + j * 16);
            ldsm_x2_t(bl[j], bBL + off + j * 16);
        }
        #pragma unroll
        for (int i = 0; i < 4; i++)
            #pragma unroll
            for (int j = 0; j < 4; j++) {
                mma_bf16(acc[i][j], ah[i], bh[j]);
                mma_bf16(acc[i][j], ah[i], bl[j]);
                mma_bf16(acc[i][j], al[i], bh[j]);
            }
        if (s + 2 < 64) CP_WAIT(1); else CP_WAIT(0);
        __syncthreads();
        cur++; if (cur == 3) cur = 0;
    }

    const int q = lane >> 2, r4 = lane & 3;
    #pragma unroll
    for (int i = 0; i < 4; i++) {
        const int lr0 = wm + i * 16 + q, lr1 = lr0 + 8;
        const bool ok0 = (m0 + lr0) < cnt, ok1 = (m0 + lr1) < cnt;
        float* d0 = g_rbuf + (size_t)s_dst[lr0] * DIM + n0;
        float* d1 = g_rbuf + (size_t)s_dst[lr1] * DIM + n0;
        #pragma unroll
        for (int j = 0; j < 4; j++) {
            const int col = wn + j * 8 + r4 * 2;
            if (ok0) *(float2*)(d0 + col) = make_float2(acc[i][j][0], acc[i][j][1]);
            if (ok1) *(float2*)(d1 + col) = make_float2(acc[i][j][2], acc[i][j][3]);
        }
    }
#undef G2_LOAD
}

// ---------------- combine ---------------------------------------------------
__global__ void combine_kernel(float* __restrict__ out) {
    int i4 = blockIdx.x * 256 + threadIdx.x;
    int t  = i4 >> 8;
    float w0 = g_top_w[2 * t], w1 = g_top_w[2 * t + 1];
    float4 a = ((const float4*)g_rbuf)[i4];
    float4 b = ((const float4*)g_rbuf)[(size_t)(N_TOK * DIM / 4) + i4];
    float4 c = ((const float4*)g_rbuf)[(size_t)(2 * N_TOK * DIM / 4) + i4];
    float4 o;
    o.x = c.x + w0 * a.x + w1 * b.x;
    o.y = c.y + w0 * a.y + w1 * b.y;
    o.z = c.z + w0 * a.z + w1 * b.z;
    o.w = c.w + w0 * a.w + w1 * b.w;
    ((float4*)out)[i4] = o;
}

// ---------------- launch ----------------------------------------------------
extern "C" void kernel_launch(void* const* d_in, const int* in_sizes, int n_in,
                              void* d_out, int out_size)
{
    const float* x  = (const float*)d_in[0];
    const float* sg = (const float*)d_in[1];
    const float* su = (const float*)d_in[2];
    const float* sd = (const float*)d_in[3];
    const float* Wg = (const float*)d_in[4];
    const float* Wu = (const float*)d_in[5];
    const float* Wd = (const float*)d_in[6];
    const float* Wr = (const float*)d_in[7];
    const float* lt = (const float*)d_in[8];
    const int*   li = (const int*)d_in[9];
    float* out = (float*)d_out;
    (void)in_sizes; (void)n_in; (void)out_size;

    static int attr_done = 0;
    if (!attr_done) {
        cudaFuncSetAttribute(gemm1_kernel, cudaFuncAttributeMaxDynamicSharedMemorySize, 3 * G1_STG);
        cudaFuncSetAttribute(gemm2_kernel, cudaFuncAttributeMaxDynamicSharedMemorySize, 3 * G2_STG);
        attr_done = 1;
    }

    zero_kernel<<<1, 32>>>();
    convert_x_kernel<<<(N_TOK * DIM / 4) / 256, 256>>>(x);
    convert_w_kernel<<<dim3((DIM * HID / 4) / 256, 27), 256>>>(Wg, Wu, Wd, sg, su, sd);
    router_kernel<<<N_TOK / 32, 256>>>(x, Wr, lt, li);
    dispatch_kernel<<<N_TOK / 256, 256>>>();

    gemm1_kernel<<<dim3(HID / 64, N_TOK / 128, NSEG), 256, 3 * G1_STG>>>();
    gemm2_kernel<<<dim3(DIM / 128, N_TOK / 128, NSEG), 256, 3 * G2_STG>>>();
    combine_kernel<<<(N_TOK * (DIM / 4)) / 256, 256>>>(out);
}